// round 5
// baseline (speedup 1.0000x reference)
#include <cuda_runtime.h>
#include <cuda_bf16.h>
#include <cuda_fp16.h>
#include <cstdint>

// Problem constants
#define NB     64
#define CIN    64
#define COUT   128
#define NT     300
#define NV     25
#define TV     7500
#define TT     5
#define NTILE  125
#define NTILES 60
#define NCNT   480000

// Scratch: y fp16, padded layout [b][o][tile][128]
__device__ __half g_ys[(size_t)NB * COUT * NTILES * 128];
__device__ float g_sum[COUT];
__device__ float g_sq[COUT];
__device__ float g_scale[COUT];
__device__ float g_shift[COUT];
// Presplit W tiles in smem-ready layout [o=128][stride 72] bf16
__device__ __nv_bfloat16 g_whi[128 * 72];
__device__ __nv_bfloat16 g_wlo[128 * 72];

typedef unsigned long long ull;

// ---------------- SMEM layout (bytes) ----------------
#define A_STR     72
#define B_STR     136
#define OFF_WHI   0          // 18432
#define OFF_WLO   18432      // 18432
#define OFF_BHI   36864      // 17408
#define OFF_BLO   54272      // 17408  (BHI+BLO = 34816 = epilogue staging 128*136*2)
#define OFF_X     71680      // 64*125*4 = 32000
#define OFF_ADJ   103680     // 2600
#define OFF_SSUM  106280     // 512
#define OFF_SSQ   106792     // 512
#define OFF_BIAS  107304     // 512
#define SMEM_BYTES 107816

__device__ __forceinline__ uint32_t smem_u32(const void* p) {
    uint32_t a;
    asm("{ .reg .u64 t; cvta.to.shared.u64 t, %1; cvt.u32.u64 %0, t; }" : "=r"(a) : "l"(p));
    return a;
}
__device__ __forceinline__ ull dup2(float x) {
    ull r; asm("mov.b64 %0, {%1, %1};" : "=l"(r) : "f"(x)); return r;
}
__device__ __forceinline__ void fma2(ull& d, ull a, ull b) {
    asm("fma.rn.f32x2 %0, %1, %2, %3;" : "=l"(d) : "l"(a), "l"(b), "l"(d));
}
__device__ __forceinline__ float2 unpk(ull v) {
    float2 f; asm("mov.b64 {%0, %1}, %2;" : "=f"(f.x), "=f"(f.y) : "l"(v)); return f;
}
__device__ __forceinline__ void ldm_x4(uint32_t* r, uint32_t addr) {
    asm volatile("ldmatrix.sync.aligned.m8n8.x4.shared.b16 {%0,%1,%2,%3}, [%4];"
        : "=r"(r[0]), "=r"(r[1]), "=r"(r[2]), "=r"(r[3]) : "r"(addr));
}
__device__ __forceinline__ void ldm_x4_t(uint32_t* r, uint32_t addr) {
    asm volatile("ldmatrix.sync.aligned.m8n8.x4.trans.shared.b16 {%0,%1,%2,%3}, [%4];"
        : "=r"(r[0]), "=r"(r[1]), "=r"(r[2]), "=r"(r[3]) : "r"(addr));
}
__device__ __forceinline__ void mma16816(float* d, const uint32_t* a, uint32_t b0, uint32_t b1) {
    asm volatile("mma.sync.aligned.m16n8k16.row.col.f32.bf16.bf16.f32 "
        "{%0,%1,%2,%3}, {%4,%5,%6,%7}, {%8,%9}, {%0,%1,%2,%3};"
        : "+f"(d[0]), "+f"(d[1]), "+f"(d[2]), "+f"(d[3])
        : "r"(a[0]), "r"(a[1]), "r"(a[2]), "r"(a[3]), "r"(b0), "r"(b1));
}
__device__ __forceinline__ uint32_t pack_half2(float a, float b) {
    __half2 h = __floats2half2_rn(a, b);
    return *(uint32_t*)&h;
}

__global__ void k0_zero() {
    int t = threadIdx.x;
    if (t < COUT) g_sum[t] = 0.f;
    else if (t < 2 * COUT) g_sq[t - COUT] = 0.f;
}

__global__ void kW_split(const float* __restrict__ W) {
    int idx = blockIdx.x * 256 + threadIdx.x;
    if (idx < COUT * CIN) {
        int o = idx >> 6, c = idx & 63;
        float v = W[idx];
        __nv_bfloat16 h = __float2bfloat16_rn(v);
        g_whi[o * A_STR + c] = h;
        g_wlo[o * A_STR + c] = __float2bfloat16_rn(v - __bfloat162float(h));
    }
}

__global__ void kNop() {}

__global__ void __launch_bounds__(256, 2)
k1_fused(const float* __restrict__ x, const float* __restrict__ adj,
         const float* __restrict__ bias)
{
    extern __shared__ char sm[];
    const uint32_t smb = smem_u32(sm);
    float* s_x    = (float*)(sm + OFF_X);
    float* s_adj  = (float*)(sm + OFF_ADJ);
    float* s_sum  = (float*)(sm + OFF_SSUM);
    float* s_sq   = (float*)(sm + OFF_SSQ);
    float* s_bias = (float*)(sm + OFF_BIAS);
    __nv_bfloat16* bhi = (__nv_bfloat16*)(sm + OFF_BHI);
    __nv_bfloat16* blo = (__nv_bfloat16*)(sm + OFF_BLO);

    const int tid = threadIdx.x;
    const int wid = tid >> 5;
    const int lid = tid & 31;
    const int blk = blockIdx.x;
    const int b   = blk / NTILES;
    const int tt  = blk - b * NTILES;

    // ---- prologue ----
    // presplit W tiles: gmem -> smem, uint4 (layout-identical)
    {
        const uint4* srcA = (const uint4*)g_whi;
        uint4* dstA = (uint4*)(sm + OFF_WHI);
        const uint4* srcB = (const uint4*)g_wlo;
        uint4* dstB = (uint4*)(sm + OFF_WLO);
        #pragma unroll
        for (int k = 0; k < 5; ++k) {   // ceil(1152/256)=5 per array
            int i = tid + k * 256;
            if (i < (128 * A_STR * 2) / 16) { dstA[i] = srcA[i]; dstB[i] = srcB[i]; }
        }
    }
    // x tile: coalesced LDG -> smem stride 125 (per warp: 8 c-rows)
    {
        const float* xb = x + (size_t)b * CIN * TV + (size_t)tt * NTILE;
        #pragma unroll
        for (int r = 0; r < 8; ++r) {
            int c = wid * 8 + r;
            const float* src = xb + (size_t)c * TV;
            float* dst = s_x + c * NTILE;
            #pragma unroll
            for (int q = 0; q < 4; ++q) {
                int j = lid + q * 32;
                if (j < NTILE) dst[j] = __ldg(src + j);
            }
        }
    }
    for (int idx = tid; idx < 650; idx += 256) {
        int v = idx / 26, w = idx - v * 26;
        s_adj[idx] = (w < NV) ? adj[v * NV + w] : 0.f;
    }
    if (tid < COUT) { s_bias[tid] = bias[tid]; s_sum[tid] = 0.f; s_sq[tid] = 0.f; }
    if (tid < 128) {  // zero B pad cols 125..127
        int c = tid & 63;
        __nv_bfloat16* bt = (tid < 64) ? bhi : blo;
        bt[c * B_STR + 125] = __nv_bfloat16(0.f);
        bt[c * B_STR + 126] = __nv_bfloat16(0.f);
        bt[c * B_STR + 127] = __nv_bfloat16(0.f);
    }
    __syncthreads();

    // ---- adjacency (fp32/f32x2) from smem x -> bf16 hi/lo B tiles ----
    for (int task = tid; task < CIN * TT; task += 256) {
        int c = task / TT, tl = task - c * TT;
        const float* xr_ptr = s_x + c * NTILE + tl * NV;   // stride-25: conflict-free
        float xr[NV];
        #pragma unroll
        for (int v = 0; v < NV; ++v) xr[v] = xr_ptr[v];
        ull acc[13];
        #pragma unroll
        for (int p = 0; p < 13; ++p) acc[p] = 0ull;
        #pragma unroll
        for (int v = 0; v < NV; ++v) {
            ull xv = dup2(xr[v]);
            const ull* arow = (const ull*)(s_adj + v * 26);
            #pragma unroll
            for (int p = 0; p < 13; ++p) fma2(acc[p], xv, arow[p]);
        }
        __nv_bfloat16* bh = bhi + c * B_STR + tl * NV;
        __nv_bfloat16* bl = blo + c * B_STR + tl * NV;
        #pragma unroll
        for (int p = 0; p < 13; ++p) {
            float2 f = unpk(acc[p]);
            int w = 2 * p;
            {
                __nv_bfloat16 h = __float2bfloat16_rn(f.x);
                bh[w] = h; bl[w] = __float2bfloat16_rn(f.x - __bfloat162float(h));
            }
            if (w + 1 < NV) {
                __nv_bfloat16 h = __float2bfloat16_rn(f.y);
                bh[w + 1] = h; bl[w + 1] = __float2bfloat16_rn(f.y - __bfloat162float(h));
            }
        }
    }
    __syncthreads();

    // ---- HMMA GEMM: D[128o][128j], 3-term bf16 split ----
    const int warpM = wid >> 1;
    const int warpN = wid & 1;
    const int mbase = warpM * 32;
    const int nbase = warpN * 64;
    const int lrow  = lid & 15;
    const int lcol8 = (lid >> 4) * 8;

    float acc[2][8][4];
    #pragma unroll
    for (int mt = 0; mt < 2; ++mt)
        #pragma unroll
        for (int nt = 0; nt < 8; ++nt)
            #pragma unroll
            for (int e = 0; e < 4; ++e) acc[mt][nt][e] = 0.f;

    #pragma unroll
    for (int ks = 0; ks < 4; ++ks) {
        uint32_t ahi[2][4], alo[2][4];
        #pragma unroll
        for (int mt = 0; mt < 2; ++mt) {
            uint32_t arow = mbase + mt * 16 + lrow;
            uint32_t acolb = ks * 16 + lcol8;
            ldm_x4(ahi[mt], smb + OFF_WHI + (arow * A_STR + acolb) * 2);
            ldm_x4(alo[mt], smb + OFF_WLO + (arow * A_STR + acolb) * 2);
        }
        #pragma unroll
        for (int nh = 0; nh < 2; ++nh) {
            uint32_t bhF[2][4], blF[2][4];
            #pragma unroll
            for (int nt2 = 0; nt2 < 2; ++nt2) {
                uint32_t brow = ks * 16 + lrow;
                uint32_t bcol = nbase + nh * 32 + nt2 * 16 + lcol8;
                ldm_x4_t(bhF[nt2], smb + OFF_BHI + (brow * B_STR + bcol) * 2);
                ldm_x4_t(blF[nt2], smb + OFF_BLO + (brow * B_STR + bcol) * 2);
            }
            #pragma unroll
            for (int mt = 0; mt < 2; ++mt)
                #pragma unroll
                for (int nt = 0; nt < 4; ++nt) {
                    float* d = acc[mt][nh * 4 + nt];
                    uint32_t b0h = bhF[nt >> 1][(nt & 1) * 2], b1h = bhF[nt >> 1][(nt & 1) * 2 + 1];
                    uint32_t b0l = blF[nt >> 1][(nt & 1) * 2], b1l = blF[nt >> 1][(nt & 1) * 2 + 1];
                    mma16816(d, ahi[mt], b0h, b1h);
                    mma16816(d, ahi[mt], b0l, b1l);
                    mma16816(d, alo[mt], b0h, b1h);
                }
        }
    }

    // ---- bias + stats ----
    const int qrow = lid >> 2;
    const int qcol = (lid & 3) * 2;
    float rsum[2][2] = {{0.f, 0.f}, {0.f, 0.f}};
    float rsq[2][2]  = {{0.f, 0.f}, {0.f, 0.f}};
    #pragma unroll
    for (int mt = 0; mt < 2; ++mt) {
        int r0 = mbase + mt * 16 + qrow;
        float b0 = s_bias[r0], b1 = s_bias[r0 + 8];
        #pragma unroll
        for (int nt = 0; nt < 8; ++nt) {
            int j0 = nbase + nt * 8 + qcol;
            float* d = acc[mt][nt];
            d[0] += b0; d[1] += b0; d[2] += b1; d[3] += b1;
            if (j0 < NTILE)     { rsum[mt][0] += d[0]; rsq[mt][0] += d[0] * d[0];
                                  rsum[mt][1] += d[2]; rsq[mt][1] += d[2] * d[2]; }
            if (j0 + 1 < NTILE) { rsum[mt][0] += d[1]; rsq[mt][0] += d[1] * d[1];
                                  rsum[mt][1] += d[3]; rsq[mt][1] += d[3] * d[3]; }
        }
    }
    #pragma unroll
    for (int mt = 0; mt < 2; ++mt)
        #pragma unroll
        for (int rr = 0; rr < 2; ++rr) {
            float s = rsum[mt][rr], q = rsq[mt][rr];
            s += __shfl_xor_sync(0xffffffffu, s, 1); q += __shfl_xor_sync(0xffffffffu, q, 1);
            s += __shfl_xor_sync(0xffffffffu, s, 2); q += __shfl_xor_sync(0xffffffffu, q, 2);
            if ((lid & 3) == 0) {
                int o = mbase + mt * 16 + qrow + rr * 8;
                atomicAdd(&s_sum[o], s);
                atomicAdd(&s_sq[o], q);
            }
        }
    __syncthreads();   // B tiles no longer needed -> staging may overwrite

    if (tid < COUT) {
        atomicAdd(&g_sum[tid], s_sum[tid]);
        atomicAdd(&g_sq[tid], s_sq[tid]);
    }
    // fragments -> fp16 staging (stride 136 halves), aliased on B tiles
    {
        uint32_t* stage = (uint32_t*)(sm + OFF_BHI);
        #pragma unroll
        for (int mt = 0; mt < 2; ++mt) {
            int r0 = mbase + mt * 16 + qrow;
            #pragma unroll
            for (int nt = 0; nt < 8; ++nt) {
                float* d = acc[mt][nt];
                int j0 = nbase + nt * 8 + qcol;
                stage[(r0 * B_STR + j0) >> 1]       = pack_half2(d[0], d[1]);
                stage[((r0 + 8) * B_STR + j0) >> 1] = pack_half2(d[2], d[3]);
            }
        }
    }
    __syncthreads();

    // staging -> gmem fp16 scratch (128B per thread, coalesced)
    {
        const __half* stage = (const __half*)(sm + OFF_BHI);
        int o  = tid >> 1;
        int hs = tid & 1;
        const uint4* src = (const uint4*)(stage + o * B_STR + hs * 64);
        uint4* dst = (uint4*)(g_ys + ((size_t)(b * COUT + o) * NTILES + tt) * 128 + hs * 64);
        #pragma unroll
        for (int k = 0; k < 8; ++k) dst[k] = src[k];
    }
}

__global__ void k2_finalize(const float* __restrict__ gamma, const float* __restrict__ beta) {
    int i = threadIdx.x;
    float mean = g_sum[i] * (1.0f / NCNT);
    float var  = g_sq[i]  * (1.0f / NCNT) - mean * mean;
    float sc   = gamma[i] * rsqrtf(var + 1e-5f);
    g_scale[i] = sc;
    g_shift[i] = beta[i] - mean * sc;
}

// block = (row, group of 4 tiles); thread t<252: tile=t/63, pair p=t%63 -> cols 2p,2p+1
__global__ void __launch_bounds__(256)
k3_norm(float* __restrict__ out) {
    int bid = blockIdx.x;
    int row = bid / 15;            // b*128+o
    int tg  = bid - row * 15;      // tile group (4 tiles)
    int t = threadIdx.x;
    if (t >= 252) return;
    int tile = t / 63;
    int p = t - tile * 63;
    int tt = tg * 4 + tile;
    int o = row & 127;
    float sc = g_scale[o], sh = g_shift[o];
    const __half2 h2 = *(const __half2*)(g_ys + ((size_t)row * NTILES + tt) * 128 + 2 * p);
    float2 f = __half22float2(h2);
    float r0 = fmaxf(fmaf(f.x, sc, sh), 0.f);
    float r1 = fmaxf(fmaf(f.y, sc, sh), 0.f);
    float* dst = out + (size_t)row * TV + tt * NTILE + 2 * p;
    dst[0] = r0;
    if (p < 62) dst[1] = r1;       // col 125 is pad
}

extern "C" void kernel_launch(void* const* d_in, const int* in_sizes, int n_in,
                              void* d_out, int out_size)
{
    (void)in_sizes; (void)n_in; (void)out_size;
    const float* x     = (const float*)d_in[0];
    const float* adj   = (const float*)d_in[1];
    const float* W     = (const float*)d_in[2];
    const float* bias  = (const float*)d_in[3];
    const float* gamma = (const float*)d_in[4];
    const float* beta  = (const float*)d_in[5];
    float* out = (float*)d_out;

    cudaFuncSetAttribute(k1_fused, cudaFuncAttributeMaxDynamicSharedMemorySize, SMEM_BYTES);

    k0_zero<<<1, 256>>>();
    kW_split<<<32, 256>>>(W);
    kNop<<<1, 32>>>();
    k1_fused<<<NB * NTILES, 256, SMEM_BYTES>>>(x, adj, bias);   // <- launch slot 6 overall?
    k2_finalize<<<1, 128>>>(gamma, beta);
    k3_norm<<<8192 * 15, 256>>>(out);
}

// round 6
// speedup vs baseline: 1.1820x; 1.1820x over previous
#include <cuda_runtime.h>
#include <cuda_bf16.h>
#include <cuda_fp16.h>
#include <cstdint>

// Problem constants
#define NB     64
#define CIN    64
#define COUT   128
#define NT     300
#define NV     25
#define TV     7500
#define TT     5
#define NTILE  125
#define NTILES 60
#define NCNT   480000

// Scratch: y fp16, padded layout [b][o][tile][128]
__device__ __half g_ys[(size_t)NB * COUT * NTILES * 128];
__device__ float g_sum[COUT];
__device__ float g_sq[COUT];
__device__ float g_scale[COUT];
__device__ float g_shift[COUT];
// Presplit W (fp16 hi/lo) in smem-ready layout [o=128][stride 72]
__device__ __half g_whi[128 * 72];
__device__ __half g_wlo[128 * 72];

typedef unsigned long long ull;

// ---------------- SMEM layout (bytes) ----------------
// A tiles: [o=128][c] fp16, stride 72 halves -> conflict-free ldmatrix
// B tile:  [c=64][j] fp16, stride 136 halves -> conflict-free ldmatrix.trans
// Epilogue staging (fp16 y, [o=128][j] stride 136 = 34816B) aliases B + spare.
#define A_STR     72
#define B_STR     136
#define OFF_WHI   0          // 18432
#define OFF_WLO   18432      // 18432
#define OFF_B     36864      // 17408 (+17408 spare for staging alias -> 71680)
#define OFF_ADJ   71680      // 2600
#define OFF_SSUM  74280      // 512
#define OFF_SSQ   74792      // 512
#define OFF_BIAS  75304      // 512
#define SMEM_BYTES 75816

__device__ __forceinline__ uint32_t smem_u32(const void* p) {
    uint32_t a;
    asm("{ .reg .u64 t; cvta.to.shared.u64 t, %1; cvt.u32.u64 %0, t; }" : "=r"(a) : "l"(p));
    return a;
}
__device__ __forceinline__ ull dup2(float x) {
    ull r; asm("mov.b64 %0, {%1, %1};" : "=l"(r) : "f"(x)); return r;
}
__device__ __forceinline__ void fma2(ull& d, ull a, ull b) {
    asm("fma.rn.f32x2 %0, %1, %2, %3;" : "=l"(d) : "l"(a), "l"(b), "l"(d));
}
__device__ __forceinline__ float2 unpk(ull v) {
    float2 f; asm("mov.b64 {%0, %1}, %2;" : "=f"(f.x), "=f"(f.y) : "l"(v)); return f;
}
__device__ __forceinline__ void ldm_x4(uint32_t* r, uint32_t addr) {
    asm volatile("ldmatrix.sync.aligned.m8n8.x4.shared.b16 {%0,%1,%2,%3}, [%4];"
        : "=r"(r[0]), "=r"(r[1]), "=r"(r[2]), "=r"(r[3]) : "r"(addr));
}
__device__ __forceinline__ void ldm_x4_t(uint32_t* r, uint32_t addr) {
    asm volatile("ldmatrix.sync.aligned.m8n8.x4.trans.shared.b16 {%0,%1,%2,%3}, [%4];"
        : "=r"(r[0]), "=r"(r[1]), "=r"(r[2]), "=r"(r[3]) : "r"(addr));
}
__device__ __forceinline__ void mma16816(float* d, const uint32_t* a, uint32_t b0, uint32_t b1) {
    asm volatile("mma.sync.aligned.m16n8k16.row.col.f32.f16.f16.f32 "
        "{%0,%1,%2,%3}, {%4,%5,%6,%7}, {%8,%9}, {%0,%1,%2,%3};"
        : "+f"(d[0]), "+f"(d[1]), "+f"(d[2]), "+f"(d[3])
        : "r"(a[0]), "r"(a[1]), "r"(a[2]), "r"(a[3]), "r"(b0), "r"(b1));
}
__device__ __forceinline__ uint32_t pack_half2(float a, float b) {
    __half2 h = __floats2half2_rn(a, b);
    return *(uint32_t*)&h;
}

__global__ void k0_zero() {
    int t = threadIdx.x;
    if (t < COUT) g_sum[t] = 0.f;
    else if (t < 2 * COUT) g_sq[t - COUT] = 0.f;
}

__global__ void kW_split(const float* __restrict__ W) {
    int idx = blockIdx.x * 256 + threadIdx.x;
    if (idx < COUT * CIN) {
        int o = idx >> 6, c = idx & 63;
        float v = W[idx];
        __half h = __float2half_rn(v);
        g_whi[o * A_STR + c] = h;
        g_wlo[o * A_STR + c] = __float2half_rn(v - __half2float(h));
    }
}

__global__ void kNop() {}

__global__ void __launch_bounds__(256, 2)
k1_fused(const float* __restrict__ x, const float* __restrict__ adj,
         const float* __restrict__ bias)
{
    extern __shared__ char sm[];
    const uint32_t smb = smem_u32(sm);
    float* s_adj  = (float*)(sm + OFF_ADJ);
    float* s_sum  = (float*)(sm + OFF_SSUM);
    float* s_sq   = (float*)(sm + OFF_SSQ);
    float* s_bias = (float*)(sm + OFF_BIAS);
    __half* sB    = (__half*)(sm + OFF_B);

    const int tid = threadIdx.x;
    const int wid = tid >> 5;
    const int lid = tid & 31;
    const int blk = blockIdx.x;
    const int b   = blk / NTILES;
    const int tt  = blk - b * NTILES;

    // ---- prologue: copy presplit W (uint4), adj, bias, zero pads/stats ----
    {
        const uint4* srcA = (const uint4*)g_whi;
        uint4* dstA = (uint4*)(sm + OFF_WHI);
        const uint4* srcB = (const uint4*)g_wlo;
        uint4* dstB = (uint4*)(sm + OFF_WLO);
        #pragma unroll
        for (int k = 0; k < 5; ++k) {   // 1152 uint4 per array
            int i = tid + k * 256;
            if (i < (128 * A_STR * 2) / 16) { dstA[i] = srcA[i]; dstB[i] = srcB[i]; }
        }
    }
    for (int idx = tid; idx < 650; idx += 256) {
        int v = idx / 26, w = idx - v * 26;
        s_adj[idx] = (w < NV) ? adj[v * NV + w] : 0.f;
    }
    if (tid < COUT) { s_bias[tid] = bias[tid]; s_sum[tid] = 0.f; s_sq[tid] = 0.f; }
    if (tid < 64) {   // zero B pad cols 125..127
        sB[tid * B_STR + 125] = __half(0.f);
        sB[tid * B_STR + 126] = __half(0.f);
        sB[tid * B_STR + 127] = __half(0.f);
    }
    __syncthreads();

    // ---- adjacency (fp32/f32x2) from gmem -> single fp16 B tile ----
    const float* xb = x + (size_t)b * CIN * TV + (size_t)tt * NTILE;
    for (int task = tid; task < CIN * TT; task += 256) {
        int c = task / TT, tl = task - c * TT;
        const float* xr_ptr = xb + (size_t)c * TV + tl * NV;
        float xr[NV];
        #pragma unroll
        for (int v = 0; v < NV; ++v) xr[v] = __ldg(xr_ptr + v);
        ull acc[13];
        #pragma unroll
        for (int p = 0; p < 13; ++p) acc[p] = 0ull;
        #pragma unroll
        for (int v = 0; v < NV; ++v) {
            ull xv = dup2(xr[v]);
            const ull* arow = (const ull*)(s_adj + v * 26);
            #pragma unroll
            for (int p = 0; p < 13; ++p) fma2(acc[p], xv, arow[p]);
        }
        __half* bh = sB + c * B_STR + tl * NV;
        #pragma unroll
        for (int p = 0; p < 13; ++p) {
            float2 f = unpk(acc[p]);
            int w = 2 * p;
            bh[w] = __float2half_rn(f.x);
            if (w + 1 < NV) bh[w + 1] = __float2half_rn(f.y);
        }
    }
    __syncthreads();

    // ---- HMMA GEMM: D[128o][128j] = Whi*B^T + Wlo*B^T (fp16, fp32 accum) ----
    const int warpM = wid >> 1;
    const int warpN = wid & 1;
    const int mbase = warpM * 32;
    const int nbase = warpN * 64;
    const int lrow  = lid & 15;
    const int lcol8 = (lid >> 4) * 8;

    float acc[2][8][4];
    #pragma unroll
    for (int mt = 0; mt < 2; ++mt)
        #pragma unroll
        for (int nt = 0; nt < 8; ++nt)
            #pragma unroll
            for (int e = 0; e < 4; ++e) acc[mt][nt][e] = 0.f;

    #pragma unroll
    for (int ks = 0; ks < 4; ++ks) {
        uint32_t ahi[2][4], alo[2][4];
        #pragma unroll
        for (int mt = 0; mt < 2; ++mt) {
            uint32_t arow = mbase + mt * 16 + lrow;
            uint32_t acolb = ks * 16 + lcol8;
            ldm_x4(ahi[mt], smb + OFF_WHI + (arow * A_STR + acolb) * 2);
            ldm_x4(alo[mt], smb + OFF_WLO + (arow * A_STR + acolb) * 2);
        }
        uint32_t bF[4][4];
        #pragma unroll
        for (int q = 0; q < 4; ++q) {
            uint32_t brow = ks * 16 + lrow;
            uint32_t bcol = nbase + q * 16 + lcol8;
            ldm_x4_t(bF[q], smb + OFF_B + (brow * B_STR + bcol) * 2);
        }
        #pragma unroll
        for (int mt = 0; mt < 2; ++mt)
            #pragma unroll
            for (int q = 0; q < 4; ++q)
                #pragma unroll
                for (int h = 0; h < 2; ++h) {
                    float* d = acc[mt][q * 2 + h];
                    uint32_t b0 = bF[q][h * 2], b1 = bF[q][h * 2 + 1];
                    mma16816(d, ahi[mt], b0, b1);
                    mma16816(d, alo[mt], b0, b1);
                }
    }

    // ---- bias + stats (quad shuffles -> smem atomics) ----
    const int qrow = lid >> 2;
    const int qcol = (lid & 3) * 2;
    float rsum[2][2] = {{0.f, 0.f}, {0.f, 0.f}};
    float rsq[2][2]  = {{0.f, 0.f}, {0.f, 0.f}};
    #pragma unroll
    for (int mt = 0; mt < 2; ++mt) {
        int r0 = mbase + mt * 16 + qrow;
        float b0 = s_bias[r0], b1 = s_bias[r0 + 8];
        #pragma unroll
        for (int nt = 0; nt < 8; ++nt) {
            int j0 = nbase + nt * 8 + qcol;
            float* d = acc[mt][nt];
            d[0] += b0; d[1] += b0; d[2] += b1; d[3] += b1;
            if (j0 < NTILE)     { rsum[mt][0] += d[0]; rsq[mt][0] += d[0] * d[0];
                                  rsum[mt][1] += d[2]; rsq[mt][1] += d[2] * d[2]; }
            if (j0 + 1 < NTILE) { rsum[mt][0] += d[1]; rsq[mt][0] += d[1] * d[1];
                                  rsum[mt][1] += d[3]; rsq[mt][1] += d[3] * d[3]; }
        }
    }
    #pragma unroll
    for (int mt = 0; mt < 2; ++mt)
        #pragma unroll
        for (int rr = 0; rr < 2; ++rr) {
            float s = rsum[mt][rr], q = rsq[mt][rr];
            s += __shfl_xor_sync(0xffffffffu, s, 1); q += __shfl_xor_sync(0xffffffffu, q, 1);
            s += __shfl_xor_sync(0xffffffffu, s, 2); q += __shfl_xor_sync(0xffffffffu, q, 2);
            if ((lid & 3) == 0) {
                int o = mbase + mt * 16 + qrow + rr * 8;
                atomicAdd(&s_sum[o], s);
                atomicAdd(&s_sq[o], q);
            }
        }
    __syncthreads();   // B tile dead -> staging may overwrite

    if (tid < COUT) {
        atomicAdd(&g_sum[tid], s_sum[tid]);
        atomicAdd(&g_sq[tid], s_sq[tid]);
    }
    // fragments -> fp16 staging [o][j] stride 136 halves (aliased on B + spare)
    {
        uint32_t* stage = (uint32_t*)(sm + OFF_B);
        #pragma unroll
        for (int mt = 0; mt < 2; ++mt) {
            int r0 = mbase + mt * 16 + qrow;
            #pragma unroll
            for (int nt = 0; nt < 8; ++nt) {
                float* d = acc[mt][nt];
                int j0 = nbase + nt * 8 + qcol;
                stage[(r0 * B_STR + j0) >> 1]       = pack_half2(d[0], d[1]);
                stage[((r0 + 8) * B_STR + j0) >> 1] = pack_half2(d[2], d[3]);
            }
        }
    }
    __syncthreads();

    // staging -> gmem fp16 scratch (128B per thread, coalesced)
    {
        const __half* stage = (const __half*)(sm + OFF_B);
        int o  = tid >> 1;
        int hs = tid & 1;
        const uint4* src = (const uint4*)(stage + o * B_STR + hs * 64);
        uint4* dst = (uint4*)(g_ys + ((size_t)(b * COUT + o) * NTILES + tt) * 128 + hs * 64);
        #pragma unroll
        for (int k = 0; k < 8; ++k) dst[k] = src[k];
    }
}

__global__ void k2_finalize(const float* __restrict__ gamma, const float* __restrict__ beta) {
    int i = threadIdx.x;
    float mean = g_sum[i] * (1.0f / NCNT);
    float var  = g_sq[i]  * (1.0f / NCNT) - mean * mean;
    float sc   = gamma[i] * rsqrtf(var + 1e-5f);
    g_scale[i] = sc;
    g_shift[i] = beta[i] - mean * sc;
}

__global__ void k3_norm(float* __restrict__ out) {
    unsigned int idx = blockIdx.x * 256u + threadIdx.x;
    unsigned int e = idx * 4u;
    if (e >= 61440000u) return;
    unsigned int row = e / TV;          // b*128+o
    int o = row & 127;
    unsigned int g = e - row * TV;
    float sc = g_scale[o], sh = g_shift[o];
    const __half* yrow = g_ys + (size_t)row * (NTILES * 128);
    float4 r;
    {
        unsigned int gg = g;     unsigned int t0 = gg / NTILE;
        r.x = fmaxf(fmaf(__half2float(yrow[t0 * 128 + (gg - t0 * NTILE)]), sc, sh), 0.f);
    }
    {
        unsigned int gg = g + 1; unsigned int t0 = gg / NTILE;
        r.y = fmaxf(fmaf(__half2float(yrow[t0 * 128 + (gg - t0 * NTILE)]), sc, sh), 0.f);
    }
    {
        unsigned int gg = g + 2; unsigned int t0 = gg / NTILE;
        r.z = fmaxf(fmaf(__half2float(yrow[t0 * 128 + (gg - t0 * NTILE)]), sc, sh), 0.f);
    }
    {
        unsigned int gg = g + 3; unsigned int t0 = gg / NTILE;
        r.w = fmaxf(fmaf(__half2float(yrow[t0 * 128 + (gg - t0 * NTILE)]), sc, sh), 0.f);
    }
    *(float4*)(out + e) = r;
}

extern "C" void kernel_launch(void* const* d_in, const int* in_sizes, int n_in,
                              void* d_out, int out_size)
{
    (void)in_sizes; (void)n_in; (void)out_size;
    const float* x     = (const float*)d_in[0];
    const float* adj   = (const float*)d_in[1];
    const float* W     = (const float*)d_in[2];
    const float* bias  = (const float*)d_in[3];
    const float* gamma = (const float*)d_in[4];
    const float* beta  = (const float*)d_in[5];
    float* out = (float*)d_out;

    cudaFuncSetAttribute(k1_fused, cudaFuncAttributeMaxDynamicSharedMemorySize, SMEM_BYTES);

    k0_zero<<<1, 256>>>();
    kW_split<<<32, 256>>>(W);
    kNop<<<1, 32>>>();
    k1_fused<<<NB * NTILES, 256, SMEM_BYTES>>>(x, adj, bias);   // ncu slot 6 -> k1
    k2_finalize<<<1, 128>>>(gamma, beta);
    k3_norm<<<60000, 256>>>(out);
}

// round 8
// speedup vs baseline: 1.5509x; 1.3121x over previous
#include <cuda_runtime.h>
#include <cuda_bf16.h>
#include <cuda_fp16.h>
#include <cstdint>

// Problem constants
#define NB     64
#define CIN    64
#define COUT   128
#define NT     300
#define NV     25
#define TV     7500
#define TT     5
#define NTILE  125
#define NTILES 60
#define NCNT   480000

// Scratch
__device__ __half g_ys[(size_t)NB * COUT * NTILES * 128];          // y fp16 [b][o][tile][128]
__device__ __half g_xg[(size_t)NB * NTILES * CIN * 136];           // xg fp16 B-tiles [b*60+tt][c][136]
__device__ float g_sum[COUT];
__device__ float g_sq[COUT];
__device__ float g_scale[COUT];
__device__ float g_shift[COUT];
__device__ __half g_whi[128 * 72];                                 // presplit W hi/lo, [o][stride 72]
__device__ __half g_wlo[128 * 72];

typedef unsigned long long ull;

#define A_STR  72
#define B_STR  136

// ---------------- kG SMEM layout (bytes) ----------------
#define OFF_WHI   0          // 18432  (staging alias [0,34816) after GEMM)
#define OFF_WLO   18432      // 18432
#define OFF_B     36864      // 17408
#define OFF_SSUM  54272      // 512
#define OFF_SSQ   54784      // 512
#define OFF_BIAS  55296      // 512
#define KG_SMEM   55808

// ---------------- kA SMEM layout (bytes) ----------------
#define KA_XSTR   754                         // floats per c-row chunk (EVEN -> float2-safe)
#define KA_OFF_X  0                           // 8*754*4 = 24128 B
#define KA_OFF_O  24128                       // 6528 halves = 13056 B ([ttl*8+c][136])
#define KA_OFF_ADJ 37184                      // 650*4 = 2600 B
#define KA_SMEM   39784

__device__ __forceinline__ uint32_t smem_u32(const void* p) {
    uint32_t a;
    asm("{ .reg .u64 t; cvta.to.shared.u64 t, %1; cvt.u32.u64 %0, t; }" : "=r"(a) : "l"(p));
    return a;
}
__device__ __forceinline__ ull dup2(float x) {
    ull r; asm("mov.b64 %0, {%1, %1};" : "=l"(r) : "f"(x)); return r;
}
__device__ __forceinline__ void fma2(ull& d, ull a, ull b) {
    asm("fma.rn.f32x2 %0, %1, %2, %3;" : "=l"(d) : "l"(a), "l"(b), "l"(d));
}
__device__ __forceinline__ float2 unpk(ull v) {
    float2 f; asm("mov.b64 {%0, %1}, %2;" : "=f"(f.x), "=f"(f.y) : "l"(v)); return f;
}
__device__ __forceinline__ void ldm_x4(uint32_t* r, uint32_t addr) {
    asm volatile("ldmatrix.sync.aligned.m8n8.x4.shared.b16 {%0,%1,%2,%3}, [%4];"
        : "=r"(r[0]), "=r"(r[1]), "=r"(r[2]), "=r"(r[3]) : "r"(addr));
}
__device__ __forceinline__ void ldm_x4_t(uint32_t* r, uint32_t addr) {
    asm volatile("ldmatrix.sync.aligned.m8n8.x4.trans.shared.b16 {%0,%1,%2,%3}, [%4];"
        : "=r"(r[0]), "=r"(r[1]), "=r"(r[2]), "=r"(r[3]) : "r"(addr));
}
__device__ __forceinline__ void mma16816(float* d, const uint32_t* a, uint32_t b0, uint32_t b1) {
    asm volatile("mma.sync.aligned.m16n8k16.row.col.f32.f16.f16.f32 "
        "{%0,%1,%2,%3}, {%4,%5,%6,%7}, {%8,%9}, {%0,%1,%2,%3};"
        : "+f"(d[0]), "+f"(d[1]), "+f"(d[2]), "+f"(d[3])
        : "r"(a[0]), "r"(a[1]), "r"(a[2]), "r"(a[3]), "r"(b0), "r"(b1));
}
__device__ __forceinline__ uint32_t pack_half2(float a, float b) {
    __half2 h = __floats2half2_rn(a, b);
    return *(uint32_t*)&h;
}

__global__ void k0_zero() {
    int t = threadIdx.x;
    if (t < COUT) g_sum[t] = 0.f;
    else if (t < 2 * COUT) g_sq[t - COUT] = 0.f;
}

__global__ void kW_split(const float* __restrict__ W) {
    int idx = blockIdx.x * 256 + threadIdx.x;
    if (idx < COUT * CIN) {
        int o = idx >> 6, c = idx & 63;
        float v = W[idx];
        __half h = __float2half_rn(v);
        g_whi[o * A_STR + c] = h;
        g_wlo[o * A_STR + c] = __float2half_rn(v - __half2float(h));
    }
}

// ---- kA: adjacency transform, fully coalesced, writes fp16 B-tiles ----
// block = (b, cg): c rows [cg*8, cg*8+8). 10 chunks of 30 t (6 tiles) each.
__global__ void __launch_bounds__(256)
kA_adj(const float* __restrict__ x, const float* __restrict__ adj)
{
    extern __shared__ char sm[];
    float*  s_x   = (float*)(sm + KA_OFF_X);
    __half* s_out = (__half*)(sm + KA_OFF_O);
    float*  s_adj = (float*)(sm + KA_OFF_ADJ);

    const int tid = threadIdx.x;
    const int b   = blockIdx.x >> 3;
    const int cg  = blockIdx.x & 7;

    for (int idx = tid; idx < 650; idx += 256) {
        int v = idx / 26, w = idx - v * 26;
        s_adj[idx] = (w < NV) ? adj[v * NV + w] : 0.f;
    }

    const float* xbase = x + ((size_t)b * CIN + cg * 8) * TV;

    for (int chunk = 0; chunk < 10; ++chunk) {
        __syncthreads();
        // load 8 rows x 750 floats, coalesced float2 (row stride 754: even -> aligned)
        for (int i = tid; i < 3000; i += 256) {
            int row = i / 375, j2 = i - row * 375;
            float2 v = *(const float2*)(xbase + (size_t)row * TV + chunk * 750 + j2 * 2);
            *(float2*)(s_x + row * KA_XSTR + j2 * 2) = v;
        }
        // zero output stage (816 uint4 = 6528 halves)
        for (int i = tid; i < 816; i += 256)
            ((uint4*)s_out)[i] = make_uint4(0u, 0u, 0u, 0u);
        __syncthreads();

        // compute: job = (c, tlocal)
        if (tid < 240) {
            int c = tid / 30, tl30 = tid - c * 30;
            int ttl = tl30 / 5, tl = tl30 - ttl * 5;
            const float* xr_ptr = s_x + c * KA_XSTR + tl30 * NV;
            float xr[NV];
            #pragma unroll
            for (int v = 0; v < NV; ++v) xr[v] = xr_ptr[v];
            ull acc[13];
            #pragma unroll
            for (int p = 0; p < 13; ++p) acc[p] = 0ull;
            #pragma unroll
            for (int v = 0; v < NV; ++v) {
                ull xv = dup2(xr[v]);
                const ull* arow = (const ull*)(s_adj + v * 26);
                #pragma unroll
                for (int p = 0; p < 13; ++p) fma2(acc[p], xv, arow[p]);
            }
            __half* dst = s_out + (ttl * 8 + c) * B_STR + tl * NV;
            #pragma unroll
            for (int p = 0; p < 13; ++p) {
                float2 f = unpk(acc[p]);
                int w = 2 * p;
                dst[w] = __float2half_rn(f.x);
                if (w + 1 < NV) dst[w + 1] = __float2half_rn(f.y);
            }
        }
        __syncthreads();

        // flush: 6 tiles x 8 c-rows x 136 halves, coalesced uint4
        {
            uint4* gbase = (uint4*)(g_xg + ((size_t)(b * NTILES + chunk * 6) * CIN + cg * 8) * B_STR);
            for (int i = tid; i < 816; i += 256) {
                int lrow = i / 17, q = i - lrow * 17;          // 136 halves = 17 uint4
                int ttl = lrow >> 3, c = lrow & 7;
                gbase[(size_t)(ttl * CIN + c) * 17 + q] = ((uint4*)s_out)[i];
            }
        }
    }
}

// ---- kG: GEMM + bias + stats + fp16 scratch write ----
__global__ void __launch_bounds__(256, 2)
kG_gemm(const float* __restrict__ bias)
{
    extern __shared__ char sm[];
    const uint32_t smb = smem_u32(sm);
    float* s_sum  = (float*)(sm + OFF_SSUM);
    float* s_sq   = (float*)(sm + OFF_SSQ);
    float* s_bias = (float*)(sm + OFF_BIAS);

    const int tid = threadIdx.x;
    const int wid = tid >> 5;
    const int lid = tid & 31;
    const int blk = blockIdx.x;
    const int b   = blk / NTILES;
    const int tt  = blk - b * NTILES;

    // ---- prologue: copy A tiles (L2-hot) + B tile, all uint4 ----
    {
        const uint4* srcA = (const uint4*)g_whi;
        uint4* dstA = (uint4*)(sm + OFF_WHI);
        const uint4* srcB = (const uint4*)g_wlo;
        uint4* dstB = (uint4*)(sm + OFF_WLO);
        #pragma unroll
        for (int k = 0; k < 5; ++k) {
            int i = tid + k * 256;
            if (i < 1152) { dstA[i] = srcA[i]; dstB[i] = srcB[i]; }
        }
        const uint4* srcX = (const uint4*)(g_xg + (size_t)(b * NTILES + tt) * CIN * B_STR);
        uint4* dstX = (uint4*)(sm + OFF_B);
        #pragma unroll
        for (int k = 0; k < 5; ++k) {
            int i = tid + k * 256;
            if (i < 1088) dstX[i] = srcX[i];
        }
    }
    if (tid < COUT) { s_bias[tid] = bias[tid]; s_sum[tid] = 0.f; s_sq[tid] = 0.f; }
    __syncthreads();

    // ---- HMMA GEMM: D[128o][128j] = Whi*B^T + Wlo*B^T ----
    const int warpM = wid >> 1;
    const int warpN = wid & 1;
    const int mbase = warpM * 32;
    const int nbase = warpN * 64;
    const int lrow  = lid & 15;
    const int lcol8 = (lid >> 4) * 8;

    float acc[2][8][4];
    #pragma unroll
    for (int mt = 0; mt < 2; ++mt)
        #pragma unroll
        for (int nt = 0; nt < 8; ++nt)
            #pragma unroll
            for (int e = 0; e < 4; ++e) acc[mt][nt][e] = 0.f;

    #pragma unroll
    for (int ks = 0; ks < 4; ++ks) {
        uint32_t ahi[2][4], alo[2][4];
        #pragma unroll
        for (int mt = 0; mt < 2; ++mt) {
            uint32_t arow = mbase + mt * 16 + lrow;
            uint32_t acolb = ks * 16 + lcol8;
            ldm_x4(ahi[mt], smb + OFF_WHI + (arow * A_STR + acolb) * 2);
            ldm_x4(alo[mt], smb + OFF_WLO + (arow * A_STR + acolb) * 2);
        }
        uint32_t bF[4][4];
        #pragma unroll
        for (int q = 0; q < 4; ++q) {
            uint32_t brow = ks * 16 + lrow;
            uint32_t bcol = nbase + q * 16 + lcol8;
            ldm_x4_t(bF[q], smb + OFF_B + (brow * B_STR + bcol) * 2);
        }
        #pragma unroll
        for (int mt = 0; mt < 2; ++mt)
            #pragma unroll
            for (int q = 0; q < 4; ++q)
                #pragma unroll
                for (int h = 0; h < 2; ++h) {
                    float* d = acc[mt][q * 2 + h];
                    uint32_t b0 = bF[q][h * 2], b1 = bF[q][h * 2 + 1];
                    mma16816(d, ahi[mt], b0, b1);
                    mma16816(d, alo[mt], b0, b1);
                }
    }

    // ---- bias + stats ----
    const int qrow = lid >> 2;
    const int qcol = (lid & 3) * 2;
    float rsum[2][2] = {{0.f, 0.f}, {0.f, 0.f}};
    float rsq[2][2]  = {{0.f, 0.f}, {0.f, 0.f}};
    #pragma unroll
    for (int mt = 0; mt < 2; ++mt) {
        int r0 = mbase + mt * 16 + qrow;
        float b0 = s_bias[r0], b1 = s_bias[r0 + 8];
        #pragma unroll
        for (int nt = 0; nt < 8; ++nt) {
            int j0 = nbase + nt * 8 + qcol;
            float* d = acc[mt][nt];
            d[0] += b0; d[1] += b0; d[2] += b1; d[3] += b1;
            if (j0 < NTILE)     { rsum[mt][0] += d[0]; rsq[mt][0] += d[0] * d[0];
                                  rsum[mt][1] += d[2]; rsq[mt][1] += d[2] * d[2]; }
            if (j0 + 1 < NTILE) { rsum[mt][0] += d[1]; rsq[mt][0] += d[1] * d[1];
                                  rsum[mt][1] += d[3]; rsq[mt][1] += d[3] * d[3]; }
        }
    }
    #pragma unroll
    for (int mt = 0; mt < 2; ++mt)
        #pragma unroll
        for (int rr = 0; rr < 2; ++rr) {
            float s = rsum[mt][rr], q = rsq[mt][rr];
            s += __shfl_xor_sync(0xffffffffu, s, 1); q += __shfl_xor_sync(0xffffffffu, q, 1);
            s += __shfl_xor_sync(0xffffffffu, s, 2); q += __shfl_xor_sync(0xffffffffu, q, 2);
            if ((lid & 3) == 0) {
                int o = mbase + mt * 16 + qrow + rr * 8;
                atomicAdd(&s_sum[o], s);
                atomicAdd(&s_sq[o], q);
            }
        }
    __syncthreads();   // A + B dead -> staging may overwrite A

    if (tid < COUT) {
        atomicAdd(&g_sum[tid], s_sum[tid]);
        atomicAdd(&g_sq[tid], s_sq[tid]);
    }
    // fragments -> fp16 staging [o][j] stride 136 halves (aliased on A tiles)
    {
        uint32_t* stage = (uint32_t*)(sm + OFF_WHI);
        #pragma unroll
        for (int mt = 0; mt < 2; ++mt) {
            int r0 = mbase + mt * 16 + qrow;
            #pragma unroll
            for (int nt = 0; nt < 8; ++nt) {
                float* d = acc[mt][nt];
                int j0 = nbase + nt * 8 + qcol;
                stage[(r0 * B_STR + j0) >> 1]       = pack_half2(d[0], d[1]);
                stage[((r0 + 8) * B_STR + j0) >> 1] = pack_half2(d[2], d[3]);
            }
        }
    }
    __syncthreads();

    // staging -> gmem fp16 scratch (128B per thread, coalesced)
    {
        const __half* stage = (const __half*)(sm + OFF_WHI);
        int o  = tid >> 1;
        int hs = tid & 1;
        const uint4* src = (const uint4*)(stage + o * B_STR + hs * 64);
        uint4* dst = (uint4*)(g_ys + ((size_t)(b * COUT + o) * NTILES + tt) * 128 + hs * 64);
        #pragma unroll
        for (int k = 0; k < 8; ++k) dst[k] = src[k];
    }
}

__global__ void k2_finalize(const float* __restrict__ gamma, const float* __restrict__ beta) {
    int i = threadIdx.x;
    float mean = g_sum[i] * (1.0f / NCNT);
    float var  = g_sq[i]  * (1.0f / NCNT) - mean * mean;
    float sc   = gamma[i] * rsqrtf(var + 1e-5f);
    g_scale[i] = sc;
    g_shift[i] = beta[i] - mean * sc;
}

__global__ void k3_norm(float* __restrict__ out) {
    unsigned int idx = blockIdx.x * 256u + threadIdx.x;
    unsigned int e = idx * 4u;
    if (e >= 61440000u) return;
    unsigned int row = e / TV;          // b*128+o
    int o = row & 127;
    unsigned int g = e - row * TV;
    float sc = g_scale[o], sh = g_shift[o];
    const __half* yrow = g_ys + (size_t)row * (NTILES * 128);
    float4 r;
    {
        unsigned int gg = g;     unsigned int t0 = gg / NTILE;
        r.x = fmaxf(fmaf(__half2float(yrow[t0 * 128 + (gg - t0 * NTILE)]), sc, sh), 0.f);
    }
    {
        unsigned int gg = g + 1; unsigned int t0 = gg / NTILE;
        r.y = fmaxf(fmaf(__half2float(yrow[t0 * 128 + (gg - t0 * NTILE)]), sc, sh), 0.f);
    }
    {
        unsigned int gg = g + 2; unsigned int t0 = gg / NTILE;
        r.z = fmaxf(fmaf(__half2float(yrow[t0 * 128 + (gg - t0 * NTILE)]), sc, sh), 0.f);
    }
    {
        unsigned int gg = g + 3; unsigned int t0 = gg / NTILE;
        r.w = fmaxf(fmaf(__half2float(yrow[t0 * 128 + (gg - t0 * NTILE)]), sc, sh), 0.f);
    }
    *(float4*)(out + e) = r;
}

extern "C" void kernel_launch(void* const* d_in, const int* in_sizes, int n_in,
                              void* d_out, int out_size)
{
    (void)in_sizes; (void)n_in; (void)out_size;
    const float* x     = (const float*)d_in[0];
    const float* adj   = (const float*)d_in[1];
    const float* W     = (const float*)d_in[2];
    const float* bias  = (const float*)d_in[3];
    const float* gamma = (const float*)d_in[4];
    const float* beta  = (const float*)d_in[5];
    float* out = (float*)d_out;

    cudaFuncSetAttribute(kA_adj,  cudaFuncAttributeMaxDynamicSharedMemorySize, KA_SMEM);
    cudaFuncSetAttribute(kG_gemm, cudaFuncAttributeMaxDynamicSharedMemorySize, KG_SMEM);

    k0_zero<<<1, 256>>>();
    kW_split<<<32, 256>>>(W);
    kA_adj<<<NB * 8, 256, KA_SMEM>>>(x, adj);
    kG_gemm<<<NB * NTILES, 256, KG_SMEM>>>(bias);     // ncu capture slot -> kG
    k2_finalize<<<1, 128>>>(gamma, beta);
    k3_norm<<<60000, 256>>>(out);
}

// round 9
// speedup vs baseline: 1.9999x; 1.2895x over previous
#include <cuda_runtime.h>
#include <cuda_bf16.h>
#include <cuda_fp16.h>
#include <cstdint>

// Problem constants
#define NB     64
#define CIN    64
#define COUT   128
#define NT     300
#define NV     25
#define TV     7500
#define TT     5
#define NTILE  125
#define NTILES 60
#define NCNT   480000
#define NTT    3840          // total tiles = NB*NTILES
#define KG_GRID 296          // persistent CTAs (2 per SM)

// Scratch
__device__ __half g_ys[(size_t)NB * COUT * NTILES * 128];   // y fp16 [b][o][tile][128]
__device__ __half g_xg[(size_t)NTT * CIN * 136];            // xg fp16 B-tiles [tile][c][136]
__device__ float g_sum[COUT];
__device__ float g_sq[COUT];
__device__ float g_scale[COUT];
__device__ float g_shift[COUT];
__device__ __half g_whi[128 * 72];
__device__ __half g_wlo[128 * 72];

typedef unsigned long long ull;

#define A_STR  72
#define B_STR  136
#define BBYTES 17408

// ---------------- kG SMEM layout (bytes) ----------------
#define OFF_WHI   0          // 18432
#define OFF_WLO   18432      // 18432
#define OFF_B0    36864      // 17408
#define OFF_B1    54272      // 17408
#define OFF_SSUM  71680      // 512
#define OFF_SSQ   72192      // 512
#define OFF_BIAS  72704      // 512
#define KG_SMEM   73216

// ---------------- kA SMEM layout (bytes) ----------------
#define KA_XSTR   754        // EVEN -> float2-safe
#define KA_OFF_X  0          // 8*754*4 = 24128
#define KA_OFF_O  24128      // 13056
#define KA_OFF_ADJ 37184     // 2600
#define KA_SMEM   39784

__device__ __forceinline__ uint32_t smem_u32(const void* p) {
    uint32_t a;
    asm("{ .reg .u64 t; cvta.to.shared.u64 t, %1; cvt.u32.u64 %0, t; }" : "=r"(a) : "l"(p));
    return a;
}
__device__ __forceinline__ ull dup2(float x) {
    ull r; asm("mov.b64 %0, {%1, %1};" : "=l"(r) : "f"(x)); return r;
}
__device__ __forceinline__ void fma2(ull& d, ull a, ull b) {
    asm("fma.rn.f32x2 %0, %1, %2, %3;" : "=l"(d) : "l"(a), "l"(b), "l"(d));
}
__device__ __forceinline__ float2 unpk(ull v) {
    float2 f; asm("mov.b64 {%0, %1}, %2;" : "=f"(f.x), "=f"(f.y) : "l"(v)); return f;
}
__device__ __forceinline__ void ldm_x4(uint32_t* r, uint32_t addr) {
    asm volatile("ldmatrix.sync.aligned.m8n8.x4.shared.b16 {%0,%1,%2,%3}, [%4];"
        : "=r"(r[0]), "=r"(r[1]), "=r"(r[2]), "=r"(r[3]) : "r"(addr));
}
__device__ __forceinline__ void ldm_x4_t(uint32_t* r, uint32_t addr) {
    asm volatile("ldmatrix.sync.aligned.m8n8.x4.trans.shared.b16 {%0,%1,%2,%3}, [%4];"
        : "=r"(r[0]), "=r"(r[1]), "=r"(r[2]), "=r"(r[3]) : "r"(addr));
}
__device__ __forceinline__ void mma16816(float* d, const uint32_t* a, uint32_t b0, uint32_t b1) {
    asm volatile("mma.sync.aligned.m16n8k16.row.col.f32.f16.f16.f32 "
        "{%0,%1,%2,%3}, {%4,%5,%6,%7}, {%8,%9}, {%0,%1,%2,%3};"
        : "+f"(d[0]), "+f"(d[1]), "+f"(d[2]), "+f"(d[3])
        : "r"(a[0]), "r"(a[1]), "r"(a[2]), "r"(a[3]), "r"(b0), "r"(b1));
}
__device__ __forceinline__ uint32_t pack_half2(float a, float b) {
    __half2 h = __floats2half2_rn(a, b);
    return *(uint32_t*)&h;
}
__device__ __forceinline__ void cp_async16(uint32_t dst, const void* src) {
    asm volatile("cp.async.cg.shared.global [%0], [%1], 16;" :: "r"(dst), "l"(src));
}
#define CP_COMMIT() asm volatile("cp.async.commit_group;" ::: "memory")
#define CP_WAIT0()  asm volatile("cp.async.wait_group 0;" ::: "memory")

__global__ void k0_zero() {
    int t = threadIdx.x;
    if (t < COUT) g_sum[t] = 0.f;
    else if (t < 2 * COUT) g_sq[t - COUT] = 0.f;
}

__global__ void kW_split(const float* __restrict__ W) {
    int idx = blockIdx.x * 256 + threadIdx.x;
    if (idx < COUT * CIN) {
        int o = idx >> 6, c = idx & 63;
        float v = W[idx];
        __half h = __float2half_rn(v);
        g_whi[o * A_STR + c] = h;
        g_wlo[o * A_STR + c] = __float2half_rn(v - __half2float(h));
    }
}

// ---- kA: adjacency, coalesced; block = (b, cg, chunk-pair) ----
__global__ void __launch_bounds__(256)
kA_adj(const float* __restrict__ x, const float* __restrict__ adj)
{
    extern __shared__ char sm[];
    float*  s_x   = (float*)(sm + KA_OFF_X);
    __half* s_out = (__half*)(sm + KA_OFF_O);
    float*  s_adj = (float*)(sm + KA_OFF_ADJ);

    const int tid = threadIdx.x;
    const int b   = blockIdx.x / 40;
    const int rem = blockIdx.x - b * 40;
    const int cg  = rem / 5;
    const int cc  = rem - cg * 5;

    for (int idx = tid; idx < 650; idx += 256) {
        int v = idx / 26, w = idx - v * 26;
        s_adj[idx] = (w < NV) ? adj[v * NV + w] : 0.f;
    }

    const float* xbase = x + ((size_t)b * CIN + cg * 8) * TV;

    for (int chunk = cc * 2; chunk < cc * 2 + 2; ++chunk) {
        __syncthreads();
        for (int i = tid; i < 3000; i += 256) {
            int row = i / 375, j2 = i - row * 375;
            float2 v = *(const float2*)(xbase + (size_t)row * TV + chunk * 750 + j2 * 2);
            *(float2*)(s_x + row * KA_XSTR + j2 * 2) = v;
        }
        for (int i = tid; i < 816; i += 256)
            ((uint4*)s_out)[i] = make_uint4(0u, 0u, 0u, 0u);
        __syncthreads();

        if (tid < 240) {
            int c = tid / 30, tl30 = tid - c * 30;
            int ttl = tl30 / 5, tl = tl30 - ttl * 5;
            const float* xr_ptr = s_x + c * KA_XSTR + tl30 * NV;
            float xr[NV];
            #pragma unroll
            for (int v = 0; v < NV; ++v) xr[v] = xr_ptr[v];
            ull acc[13];
            #pragma unroll
            for (int p = 0; p < 13; ++p) acc[p] = 0ull;
            #pragma unroll
            for (int v = 0; v < NV; ++v) {
                ull xv = dup2(xr[v]);
                const ull* arow = (const ull*)(s_adj + v * 26);
                #pragma unroll
                for (int p = 0; p < 13; ++p) fma2(acc[p], xv, arow[p]);
            }
            __half* dst = s_out + (ttl * 8 + c) * B_STR + tl * NV;
            #pragma unroll
            for (int p = 0; p < 13; ++p) {
                float2 f = unpk(acc[p]);
                int w = 2 * p;
                dst[w] = __float2half_rn(f.x);
                if (w + 1 < NV) dst[w + 1] = __float2half_rn(f.y);
            }
        }
        __syncthreads();

        {
            uint4* gbase = (uint4*)(g_xg + ((size_t)(b * NTILES + chunk * 6) * CIN + cg * 8) * B_STR);
            for (int i = tid; i < 816; i += 256) {
                int lrow = i / 17, q = i - lrow * 17;
                int ttl = lrow >> 3, c = lrow & 7;
                gbase[(size_t)(ttl * CIN + c) * 17 + q] = ((uint4*)s_out)[i];
            }
        }
    }
}

// ---- kG: persistent, double-buffered B via cp.async ----
__global__ void __launch_bounds__(256, 2)
kG_gemm(const float* __restrict__ bias)
{
    extern __shared__ char sm[];
    const uint32_t smb = smem_u32(sm);
    float* s_sum  = (float*)(sm + OFF_SSUM);
    float* s_sq   = (float*)(sm + OFF_SSQ);
    float* s_bias = (float*)(sm + OFF_BIAS);

    const int tid = threadIdx.x;
    const int wid = tid >> 5;
    const int lid = tid & 31;

    // ---- prologue: W + first B via cp.async ----
    #pragma unroll
    for (int k = 0; k < 5; ++k) {
        int i = tid + k * 256;
        if (i < 1152) {
            cp_async16(smb + OFF_WHI + i * 16, (const char*)g_whi + i * 16);
            cp_async16(smb + OFF_WLO + i * 16, (const char*)g_wlo + i * 16);
        }
    }
    {
        const char* src = (const char*)(g_xg + (size_t)blockIdx.x * (CIN * B_STR));
        #pragma unroll
        for (int k = 0; k < 5; ++k) {
            int i = tid + k * 256;
            if (i < 1088) cp_async16(smb + OFF_B0 + i * 16, src + i * 16);
        }
    }
    CP_COMMIT();
    if (tid < COUT) { s_bias[tid] = bias[tid]; s_sum[tid] = 0.f; s_sq[tid] = 0.f; }
    CP_WAIT0();
    __syncthreads();

    const int warpM = wid >> 1;
    const int warpN = wid & 1;
    const int mbase = warpM * 32;
    const int nbase = warpN * 64;
    const int lrow  = lid & 15;
    const int lcol8 = (lid >> 4) * 8;
    const int qrow  = lid >> 2;
    const int qcol  = (lid & 3) * 2;

    float tsum[2][2] = {{0.f, 0.f}, {0.f, 0.f}};
    float tsq[2][2]  = {{0.f, 0.f}, {0.f, 0.f}};

    int p = 0;
    for (int t = blockIdx.x; t < NTT; t += KG_GRID) {
        const int b  = t / NTILES;
        const int tt = t - b * NTILES;
        const int tn = t + KG_GRID;

        // prefetch next tile's B into alternate buffer (overlaps MMA)
        if (tn < NTT) {
            const char* src = (const char*)(g_xg + (size_t)tn * (CIN * B_STR));
            uint32_t dstb = smb + OFF_B0 + (p ^ 1) * BBYTES;
            #pragma unroll
            for (int k = 0; k < 5; ++k) {
                int i = tid + k * 256;
                if (i < 1088) cp_async16(dstb + i * 16, src + i * 16);
            }
            CP_COMMIT();
        }

        // ---- MMA on buf[p] ----
        const uint32_t offB = OFF_B0 + p * BBYTES;
        float acc[2][8][4];
        #pragma unroll
        for (int mt = 0; mt < 2; ++mt)
            #pragma unroll
            for (int nt = 0; nt < 8; ++nt)
                #pragma unroll
                for (int e = 0; e < 4; ++e) acc[mt][nt][e] = 0.f;

        #pragma unroll
        for (int ks = 0; ks < 4; ++ks) {
            uint32_t ahi[2][4], alo[2][4];
            #pragma unroll
            for (int mt = 0; mt < 2; ++mt) {
                uint32_t arow = mbase + mt * 16 + lrow;
                uint32_t acolb = ks * 16 + lcol8;
                ldm_x4(ahi[mt], smb + OFF_WHI + (arow * A_STR + acolb) * 2);
                ldm_x4(alo[mt], smb + OFF_WLO + (arow * A_STR + acolb) * 2);
            }
            uint32_t bF[4][4];
            #pragma unroll
            for (int q = 0; q < 4; ++q) {
                uint32_t brow = ks * 16 + lrow;
                uint32_t bcol = nbase + q * 16 + lcol8;
                ldm_x4_t(bF[q], smb + offB + (brow * B_STR + bcol) * 2);
            }
            #pragma unroll
            for (int mt = 0; mt < 2; ++mt)
                #pragma unroll
                for (int q = 0; q < 4; ++q)
                    #pragma unroll
                    for (int h = 0; h < 2; ++h) {
                        float* d = acc[mt][q * 2 + h];
                        uint32_t b0 = bF[q][h * 2], b1 = bF[q][h * 2 + 1];
                        mma16816(d, ahi[mt], b0, b1);
                        mma16816(d, alo[mt], b0, b1);
                    }
        }

        // ---- bias + stats (register accumulation across tiles) ----
        #pragma unroll
        for (int mt = 0; mt < 2; ++mt) {
            int r0 = mbase + mt * 16 + qrow;
            float b0 = s_bias[r0], b1 = s_bias[r0 + 8];
            #pragma unroll
            for (int nt = 0; nt < 8; ++nt) {
                int j0 = nbase + nt * 8 + qcol;
                float* d = acc[mt][nt];
                d[0] += b0; d[1] += b0; d[2] += b1; d[3] += b1;
                if (j0 < NTILE)     { tsum[mt][0] += d[0]; tsq[mt][0] += d[0] * d[0];
                                      tsum[mt][1] += d[2]; tsq[mt][1] += d[2] * d[2]; }
                if (j0 + 1 < NTILE) { tsum[mt][0] += d[1]; tsq[mt][0] += d[1] * d[1];
                                      tsum[mt][1] += d[3]; tsq[mt][1] += d[3] * d[3]; }
            }
        }
        __syncthreads();   // all reads of buf[p] done -> stage may overwrite

        uint32_t* stage = (uint32_t*)(sm + OFF_B0 + p * BBYTES);
        uint4* stage4 = (uint4*)(sm + OFF_B0 + p * BBYTES);
        const size_t yb = (size_t)b * COUT * (NTILES * 128) + (size_t)tt * 128;

        // phase 0: rows 0..63 (warps 0-3 own them)
        if (wid < 4) {
            #pragma unroll
            for (int mt = 0; mt < 2; ++mt) {
                int r0 = mbase + mt * 16 + qrow;
                #pragma unroll
                for (int nt = 0; nt < 8; ++nt) {
                    float* d = acc[mt][nt];
                    int j0 = nbase + nt * 8 + qcol;
                    stage[(r0 * B_STR + j0) >> 1]       = pack_half2(d[0], d[1]);
                    stage[((r0 + 8) * B_STR + j0) >> 1] = pack_half2(d[2], d[3]);
                }
            }
        }
        __syncthreads();
        #pragma unroll
        for (int k = 0; k < 4; ++k) {
            int idx = tid + k * 256;                 // 1024 uint4
            int row = idx >> 4, q = idx & 15;
            uint4* dst = (uint4*)(g_ys + yb + (size_t)row * (NTILES * 128));
            dst[q] = stage4[row * 17 + q];
        }
        __syncthreads();

        // phase 1: rows 64..127 (warps 4-7)
        if (wid >= 4) {
            #pragma unroll
            for (int mt = 0; mt < 2; ++mt) {
                int r0 = mbase + mt * 16 + qrow - 64;
                #pragma unroll
                for (int nt = 0; nt < 8; ++nt) {
                    float* d = acc[mt][nt];
                    int j0 = nbase + nt * 8 + qcol;
                    stage[(r0 * B_STR + j0) >> 1]       = pack_half2(d[0], d[1]);
                    stage[((r0 + 8) * B_STR + j0) >> 1] = pack_half2(d[2], d[3]);
                }
            }
        }
        __syncthreads();
        #pragma unroll
        for (int k = 0; k < 4; ++k) {
            int idx = tid + k * 256;
            int row = idx >> 4, q = idx & 15;
            uint4* dst = (uint4*)(g_ys + yb + (size_t)(row + 64) * (NTILES * 128));
            dst[q] = stage4[row * 17 + q];
        }
        if (tn < NTT) CP_WAIT0();
        __syncthreads();
        p ^= 1;
    }

    // ---- stats flush (once per CTA) ----
    #pragma unroll
    for (int mt = 0; mt < 2; ++mt)
        #pragma unroll
        for (int rr = 0; rr < 2; ++rr) {
            float s = tsum[mt][rr], q = tsq[mt][rr];
            s += __shfl_xor_sync(0xffffffffu, s, 1); q += __shfl_xor_sync(0xffffffffu, q, 1);
            s += __shfl_xor_sync(0xffffffffu, s, 2); q += __shfl_xor_sync(0xffffffffu, q, 2);
            if ((lid & 3) == 0) {
                int o = mbase + mt * 16 + qrow + rr * 8;
                atomicAdd(&s_sum[o], s);
                atomicAdd(&s_sq[o], q);
            }
        }
    __syncthreads();
    if (tid < COUT) {
        atomicAdd(&g_sum[tid], s_sum[tid]);
        atomicAdd(&g_sq[tid], s_sq[tid]);
    }
}

__global__ void k2_finalize(const float* __restrict__ gamma, const float* __restrict__ beta) {
    int i = threadIdx.x;
    float mean = g_sum[i] * (1.0f / NCNT);
    float var  = g_sq[i]  * (1.0f / NCNT) - mean * mean;
    float sc   = gamma[i] * rsqrtf(var + 1e-5f);
    g_scale[i] = sc;
    g_shift[i] = beta[i] - mean * sc;
}

__global__ void k3_norm(float* __restrict__ out) {
    unsigned int idx = blockIdx.x * 256u + threadIdx.x;
    unsigned int e = idx * 4u;
    if (e >= 61440000u) return;
    unsigned int row = e / TV;
    int o = row & 127;
    unsigned int g = e - row * TV;
    float sc = g_scale[o], sh = g_shift[o];
    const __half* yrow = g_ys + (size_t)row * (NTILES * 128);
    float4 r;
    {
        unsigned int gg = g;     unsigned int t0 = gg / NTILE;
        r.x = fmaxf(fmaf(__half2float(yrow[t0 * 128 + (gg - t0 * NTILE)]), sc, sh), 0.f);
    }
    {
        unsigned int gg = g + 1; unsigned int t0 = gg / NTILE;
        r.y = fmaxf(fmaf(__half2float(yrow[t0 * 128 + (gg - t0 * NTILE)]), sc, sh), 0.f);
    }
    {
        unsigned int gg = g + 2; unsigned int t0 = gg / NTILE;
        r.z = fmaxf(fmaf(__half2float(yrow[t0 * 128 + (gg - t0 * NTILE)]), sc, sh), 0.f);
    }
    {
        unsigned int gg = g + 3; unsigned int t0 = gg / NTILE;
        r.w = fmaxf(fmaf(__half2float(yrow[t0 * 128 + (gg - t0 * NTILE)]), sc, sh), 0.f);
    }
    *(float4*)(out + e) = r;
}

extern "C" void kernel_launch(void* const* d_in, const int* in_sizes, int n_in,
                              void* d_out, int out_size)
{
    (void)in_sizes; (void)n_in; (void)out_size;
    const float* x     = (const float*)d_in[0];
    const float* adj   = (const float*)d_in[1];
    const float* W     = (const float*)d_in[2];
    const float* bias  = (const float*)d_in[3];
    const float* gamma = (const float*)d_in[4];
    const float* beta  = (const float*)d_in[5];
    float* out = (float*)d_out;

    cudaFuncSetAttribute(kA_adj,  cudaFuncAttributeMaxDynamicSharedMemorySize, KA_SMEM);
    cudaFuncSetAttribute(kG_gemm, cudaFuncAttributeMaxDynamicSharedMemorySize, KG_SMEM);

    k0_zero<<<1, 256>>>();
    kW_split<<<32, 256>>>(W);
    kA_adj<<<2560, 256, KA_SMEM>>>(x, adj);
    kG_gemm<<<KG_GRID, 256, KG_SMEM>>>(bias);     // ncu capture slot -> kG
    k2_finalize<<<1, 128>>>(gamma, beta);
    k3_norm<<<60000, 256>>>(out);
}